// round 2
// baseline (speedup 1.0000x reference)
#include <cuda_runtime.h>
#include <cuda_bf16.h>
#include <cstdint>
#include <cstddef>

#define DEV __device__ __forceinline__

// ============================================================================
// Device global scratch (allocation-free rule: static __device__ arrays)
// ============================================================================
// A_perm: fragment-packed bf16 hi/lo activations.
//   Layout: [pass(2)][mt(M/16)][kt16(128)][lane(32)] x uint4 (regs a0..a3)
__device__ __align__(256) __nv_bfloat16 g_A2[(size_t)32768 * 2048];   // 128 MB
// B_perm: fragment-packed ternary bf16 weights (quaternion signs folded).
//   Layout: [nt8(256)][kt16(128)][lane(32)] x uint2 (regs b0,b1)
__device__ __align__(256) __nv_bfloat16 g_B[(size_t)2048 * 2048];     // 8 MB
__device__ float g_wmean[4];
__device__ float g_wscale[4];
__device__ float g_outscale;

// ============================================================================
// PTX helpers
// ============================================================================
DEV uint32_t smem_u32(const void* p) {
    uint32_t a;
    asm("{ .reg .u64 t; cvta.to.shared.u64 t, %1; cvt.u32.u64 %0, t; }" : "=r"(a) : "l"(p));
    return a;
}
DEV void cp_async16(uint32_t dst, const void* src) {
    asm volatile("cp.async.cg.shared.global [%0], [%1], 16;" :: "r"(dst), "l"(src) : "memory");
}
DEV void cp_commit() { asm volatile("cp.async.commit_group;" ::: "memory"); }
template <int N> DEV void cp_wait() { asm volatile("cp.async.wait_group %0;" :: "n"(N) : "memory"); }

// mma.sync m16n8k16, bf16 x bf16 -> f32
DEV void mma_bf16(float& d0, float& d1, float& d2, float& d3,
                  uint32_t a0, uint32_t a1, uint32_t a2, uint32_t a3,
                  uint32_t b0, uint32_t b1) {
    asm volatile(
        "mma.sync.aligned.m16n8k16.row.col.f32.bf16.bf16.f32 "
        "{%0,%1,%2,%3}, {%4,%5,%6,%7}, {%8,%9}, {%0,%1,%2,%3};"
        : "+f"(d0), "+f"(d1), "+f"(d2), "+f"(d3)
        : "r"(a0), "r"(a1), "r"(a2), "r"(a3), "r"(b0), "r"(b1));
}

// ============================================================================
// Kernel 1: per-weight mean / mean|w| (each block reduces one 512x512 weight)
// ============================================================================
__global__ void reduce_w_kernel(const float* __restrict__ rw, const float* __restrict__ iw,
                                const float* __restrict__ jw, const float* __restrict__ kw) {
    const float* ws[4] = {rw, iw, jw, kw};
    const float4* w4 = (const float4*)ws[blockIdx.x];
    float s = 0.f, sa = 0.f;
    for (int idx = threadIdx.x; idx < 65536; idx += 256) {
        float4 v = w4[idx];
        s  += v.x + v.y + v.z + v.w;
        sa += fabsf(v.x) + fabsf(v.y) + fabsf(v.z) + fabsf(v.w);
    }
    __shared__ float sh[64];
    for (int o = 16; o; o >>= 1) {
        s  += __shfl_down_sync(0xFFFFFFFFu, s, o);
        sa += __shfl_down_sync(0xFFFFFFFFu, sa, o);
    }
    int wid = threadIdx.x >> 5, lane = threadIdx.x & 31;
    if (lane == 0) { sh[wid] = s; sh[wid + 32] = sa; }
    __syncthreads();
    if (threadIdx.x == 0) {
        float ts = 0.f, tsa = 0.f;
        for (int q = 0; q < 8; q++) { ts += sh[q]; tsa += sh[q + 32]; }
        g_wmean[blockIdx.x]  = ts / 262144.f;
        g_wscale[blockIdx.x] = fmaxf(tsa / 262144.f, 1e-8f);
    }
}

// ============================================================================
// Quaternion block tables: block index t = (o>>9)*4 + (k>>9)
// ============================================================================
__device__ __constant__ int   c_sel[16] = {0,1,2,3,  1,0,3,2,  2,3,0,1,  3,2,1,0};
__device__ __constant__ float c_sgn[16] = {1.f,-1.f,-1.f,-1.f,  1.f,1.f,1.f,-1.f,
                                           1.f,-1.f,1.f,1.f,    1.f,1.f,-1.f,1.f};

DEV float quant_w(const float* const* ws, int o, int k) {
    int t = ((o >> 9) << 2) | (k >> 9);
    int s = c_sel[t];
    float w = __ldg(ws[s] + (size_t)(o & 511) * 512 + (k & 511));
    float q = rintf(fminf(fmaxf((w - g_wmean[s]) / g_wscale[s], -1.f), 1.f));
    return c_sgn[t] * q;
}

// ============================================================================
// Kernel 2: pack W_big into mma B-fragment layout (ternary bf16)
//   one thread per (nt8, kt16, lane): writes uint2 {b0,b1}
//   b0 = {W[o][k0], W[o][k0+1]}, b1 = {W[o][k0+8], W[o][k0+9]}
//   o = nt*8 + lane/4, k0 = kt*16 + 2*(lane%4)
// ============================================================================
__global__ void pack_w_kernel(const float* __restrict__ rw, const float* __restrict__ iw,
                              const float* __restrict__ jw, const float* __restrict__ kw) {
    int t = blockIdx.x * 256 + threadIdx.x;          // [0, 256*128*32)
    if (t == 0)
        g_outscale = (g_wscale[0] + g_wscale[1] + g_wscale[2] + g_wscale[3]) * 0.125f;
    int lane = t & 31;
    int kt   = (t >> 5) & 127;
    int nt   = t >> 12;
    int r = lane >> 2, c = lane & 3;
    int o  = nt * 8 + r;
    int k0 = kt * 16 + 2 * c;
    const float* ws[4] = {rw, iw, jw, kw};

    __nv_bfloat162 p0 = __floats2bfloat162_rn(quant_w(ws, o, k0),     quant_w(ws, o, k0 + 1));
    __nv_bfloat162 p1 = __floats2bfloat162_rn(quant_w(ws, o, k0 + 8), quant_w(ws, o, k0 + 9));
    uint2 pk;
    pk.x = *reinterpret_cast<unsigned*>(&p0);
    pk.y = *reinterpret_cast<unsigned*>(&p1);
    ((uint2*)g_B)[t] = pk;
}

// ============================================================================
// Kernel 3: split x (f32) into bf16 hi + lo, packed into mma A-fragment layout
//   one thread per (mt, kt16, lane): writes uint4 {a0..a3} for hi and for lo
//   a0={x[r][k0],x[r][k0+1]}, a1={x[r+8][k0],...}, a2={x[r][k0+8],...}, a3={x[r+8][k0+8],...}
// ============================================================================
__global__ void split_x_kernel(const float* __restrict__ x, int MT) {
    int t = blockIdx.x * 256 + threadIdx.x;          // [0, MT*128*32)
    int lane = t & 31;
    int kt   = (t >> 5) & 127;
    int mt   = t >> 12;
    int r  = lane >> 2, c = lane & 3;
    int row0 = mt * 16 + r;
    int k0   = kt * 16 + 2 * c;

    float2 v00 = *(const float2*)(x + (size_t)row0 * 2048 + k0);           // (r,   k0..k0+1)
    float2 v10 = *(const float2*)(x + (size_t)(row0 + 8) * 2048 + k0);     // (r+8, k0..k0+1)
    float2 v01 = *(const float2*)(x + (size_t)row0 * 2048 + k0 + 8);       // (r,   k0+8..9)
    float2 v11 = *(const float2*)(x + (size_t)(row0 + 8) * 2048 + k0 + 8); // (r+8, k0+8..9)

    float f[8] = {v00.x, v00.y, v10.x, v10.y, v01.x, v01.y, v11.x, v11.y};
    unsigned hip[4], lop[4];
#pragma unroll
    for (int q = 0; q < 4; q++) {
        float f0 = f[q * 2], f1 = f[q * 2 + 1];
        __nv_bfloat16 h0 = __float2bfloat16(f0);
        __nv_bfloat16 h1 = __float2bfloat16(f1);
        __nv_bfloat16 l0 = __float2bfloat16(f0 - __bfloat162float(h0));
        __nv_bfloat16 l1 = __float2bfloat16(f1 - __bfloat162float(h1));
        hip[q] = (unsigned)*(unsigned short*)&h0 | ((unsigned)*(unsigned short*)&h1 << 16);
        lop[q] = (unsigned)*(unsigned short*)&l0 | ((unsigned)*(unsigned short*)&l1 << 16);
    }
    uint4* A4 = (uint4*)g_A2;
    size_t base = ((size_t)mt * 128 + kt) * 32 + lane;
    A4[base]                            = make_uint4(hip[0], hip[1], hip[2], hip[3]);
    A4[base + (size_t)MT * 128 * 32]    = make_uint4(lop[0], lop[1], lop[2], lop[3]);
}

// ============================================================================
// Kernel 4: GEMM via mma.sync  out[M,2048] = (A(hi+lo) @ W_big^T + bias)*osc
//   CTA tile 128x128, K-tile 32 (2 x k16), 8 warps (4m x 2n, warp tile 32x64)
//   4-stage cp.async pipeline; 128 iterations = 64 ktiles x {hi, lo} pass.
// ============================================================================
static constexpr int NS = 4;
static constexpr int STAGE_BYTES = 16384;             // A 8KB + B 8KB
static constexpr int GEMM_SMEM   = NS * STAGE_BYTES;  // 64 KB

__global__ void __launch_bounds__(256, 2)
quat_gemm_kernel(float* __restrict__ out, const float* __restrict__ bias, int MT) {
    extern __shared__ char smem[];
    const uint32_t smem_base = smem_u32(smem);
    const int tid    = threadIdx.x;
    const int lane   = tid & 31;
    const int wid    = tid >> 5;
    const int warp_m = wid & 3;       // 0..3
    const int warp_n = wid >> 2;      // 0..1
    const int mtile0 = blockIdx.y * 8;    // 8 m16-tiles per CTA
    const int nt0    = blockIdx.x * 16;   // 16 n8-tiles per CTA

    const uint4* A4 = (const uint4*)g_A2;
    const uint4* B4 = (const uint4*)g_B;
    const int NIT = 128;                  // 2 passes x 64 ktile32

    float acc[2][8][4];
#pragma unroll
    for (int i = 0; i < 2; i++)
#pragma unroll
        for (int j = 0; j < 8; j++)
#pragma unroll
            for (int q = 0; q < 4; q++) acc[i][j][q] = 0.f;

    // ---- producer lambda-ish macro: fill stage s with iteration i's tiles ----
    auto issue_stage = [&](int s, int i) {
        const int pass = i >> 6;
        const int kt32 = i & 63;                  // ktile32 index -> k16 tiles {2kt32, 2kt32+1}
        const uint4* Ab = A4 + (((size_t)pass * MT + mtile0) * 128 + kt32 * 2) * 32;
        const uint4* Bb = B4 + ((size_t)nt0 * 128 + kt32 * 2) * 16;
        const uint32_t sA = smem_base + s * STAGE_BYTES;
        const uint32_t sB = sA + 8192;
#pragma unroll
        for (int u = 0; u < 2; u++) {
            int t = tid + u * 256;                // [0,512)
            // A: t = mtl(3b) | ktl(1b) | lane(5b)   gmem: mtl stride 128*32 uint4
            int mtl = t >> 6, remA = t & 63;
            cp_async16(sA + t * 16, Ab + (size_t)mtl * 4096 + remA);
            // B: t = ntl(4b) | ktl(1b) | chunk(4b)  gmem: ntl stride 128*16 uint4
            int ntl = t >> 5, remB = t & 31;
            cp_async16(sB + t * 16, Bb + (size_t)ntl * 2048 + remB);
        }
        cp_commit();
    };

    // prologue: fill stages 0..2
    issue_stage(0, 0);
    issue_stage(1, 1);
    issue_stage(2, 2);

#pragma unroll 1
    for (int i = 0; i < NIT; ++i) {
        if (i + 3 < NIT) issue_stage((i + 3) & 3, i + 3);
        else             cp_commit();            // keep group count uniform
        cp_wait<3>();
        __syncthreads();

        const int s = i & 3;
        const uint4* Asm = (const uint4*)(smem + s * STAGE_BYTES);
        const uint2* Bsm = (const uint2*)(smem + s * STAGE_BYTES + 8192);
#pragma unroll
        for (int ks = 0; ks < 2; ks++) {
            uint4 a[2];
            uint2 b[8];
#pragma unroll
            for (int mtl = 0; mtl < 2; mtl++)
                a[mtl] = Asm[((warp_m * 2 + mtl) * 2 + ks) * 32 + lane];
#pragma unroll
            for (int ntl = 0; ntl < 8; ntl++)
                b[ntl] = Bsm[((warp_n * 8 + ntl) * 2 + ks) * 32 + lane];
#pragma unroll
            for (int mtl = 0; mtl < 2; mtl++)
#pragma unroll
                for (int ntl = 0; ntl < 8; ntl++)
                    mma_bf16(acc[mtl][ntl][0], acc[mtl][ntl][1],
                             acc[mtl][ntl][2], acc[mtl][ntl][3],
                             a[mtl].x, a[mtl].y, a[mtl].z, a[mtl].w,
                             b[ntl].x, b[ntl].y);
        }
        __syncthreads();
    }

    // ---- epilogue: (acc + bias) * osc, direct float2 stores ----
    const float osc = g_outscale;
    const int r = lane >> 2, c = lane & 3;
    const int m_base = (mtile0 + warp_m * 2) * 16 + r;
    const int n_base = nt0 * 8 + warp_n * 64 + 2 * c;
#pragma unroll
    for (int mtl = 0; mtl < 2; mtl++) {
        const int mrow = m_base + mtl * 16;
#pragma unroll
        for (int ntl = 0; ntl < 8; ntl++) {
            const int nc = n_base + ntl * 8;
            float2 bv = *(const float2*)(bias + nc);
            float2 o0, o1;
            o0.x = (acc[mtl][ntl][0] + bv.x) * osc;
            o0.y = (acc[mtl][ntl][1] + bv.y) * osc;
            o1.x = (acc[mtl][ntl][2] + bv.x) * osc;
            o1.y = (acc[mtl][ntl][3] + bv.y) * osc;
            *(float2*)(out + (size_t)mrow * 2048 + nc)       = o0;
            *(float2*)(out + (size_t)(mrow + 8) * 2048 + nc) = o1;
        }
    }
}

// ============================================================================
// Host launch — graph-capturable: kernel launches only
// ============================================================================
extern "C" void kernel_launch(void* const* d_in, const int* in_sizes, int n_in,
                              void* d_out, int out_size) {
    const float* x    = (const float*)d_in[0];
    const float* rw   = (const float*)d_in[1];
    const float* iw   = (const float*)d_in[2];
    const float* jw   = (const float*)d_in[3];
    const float* kw   = (const float*)d_in[4];
    const float* bias = (const float*)d_in[5];
    float* out = (float*)d_out;
    const int M  = in_sizes[0] / 2048;   // 16384 for B=4, S=4096
    const int MT = M / 16;               // 1024 m16-tiles

    reduce_w_kernel<<<4, 256>>>(rw, iw, jw, kw);
    pack_w_kernel<<<(256 * 128 * 32) / 256, 256>>>(rw, iw, jw, kw);
    split_x_kernel<<<(MT * 128 * 32) / 256, 256>>>(x, MT);

    static int attr_done = 0;
    if (!attr_done) {
        cudaFuncSetAttribute(quat_gemm_kernel,
                             cudaFuncAttributeMaxDynamicSharedMemorySize, GEMM_SMEM);
        attr_done = 1;
    }
    dim3 grid(2048 / 128, M / 128);      // x = n-tiles fastest (A reuse in L2)
    quat_gemm_kernel<<<grid, 256, GEMM_SMEM>>>(out, bias, MT);
}